// round 5
// baseline (speedup 1.0000x reference)
#include <cuda_runtime.h>

#define FULL 0xffffffffu
typedef unsigned long long u64;

// ---- packed f32x2 helpers (Blackwell FFMA2 — only reachable via PTX) ----
__device__ __forceinline__ float2 upk2(u64 p) {
    float2 v;
    asm("mov.b64 {%0, %1}, %2;" : "=f"(v.x), "=f"(v.y) : "l"(p));
    return v;
}
__device__ __forceinline__ u64 fma2(u64 a, u64 b, u64 c) {
    u64 d;
    asm("fma.rn.f32x2 %0, %1, %2, %3;" : "=l"(d) : "l"(a), "l"(b), "l"(c));
    return d;
}
__device__ __forceinline__ u64 mul2(u64 a, u64 b) {
    u64 d;
    asm("mul.rn.f32x2 %0, %1, %2;" : "=l"(d) : "l"(a), "l"(b));
    return d;
}

// Scratch for qout: up to 16384 rows x 8 qubits (actual: 8192 rows). 512 KB.
__device__ float g_qout[16384 * 8];

// ================= Kernel 1: GEMM1 (split-K, reg-resident W1) + quantum =================
// 16 rows per 256-thread block. Warp w owns j-slice [w*128, w*128+128).
// Per row per lane: 1 LDG.128 (x), 16 FFMA2, 9-shuffle reduce, smem partial.
// Quantum (threads 0..127): z = cos(th)cos(a) - sin(th)sin(phi)sin(a);
// CNOT ring conjugated to Z-strings: qout[0]=z1..z7, qout[i]=z0..zi.
__global__ void __launch_bounds__(256, 4)
ffq_k1(const float* __restrict__ x,  const float* __restrict__ W1,
       const float* __restrict__ b1, const float* __restrict__ qp,
       int nrows)
{
    __shared__ __align__(16) float part[16][8][8];   // [row][qubit][warp]

    const int lane = threadIdx.x & 31;
    const int wid  = threadIdx.x >> 5;
    const int rowblk = blockIdx.x * 16;

    const int j0 = wid * 128 + lane * 4;

    // W1 slice register-resident for the whole block
    u64 wp0[8], wp1[8];
#pragma unroll
    for (int i = 0; i < 8; i++) {
        longlong2 w = __ldg((const longlong2*)(W1 + (size_t)i * 1024 + j0));
        wp0[i] = (u64)w.x;
        wp1[i] = (u64)w.y;
    }

#pragma unroll 4
    for (int rloc = 0; rloc < 16; rloc++) {
        const int row = min(rowblk + rloc, nrows - 1);
        longlong2 xv = __ldg((const longlong2*)(x + (size_t)row * 1024 + j0));
        const u64 x0 = (u64)xv.x, x1 = (u64)xv.y;

        float v[8];
#pragma unroll
        for (int i = 0; i < 8; i++) {
            u64 s = mul2(x0, wp0[i]);
            s = fma2(x1, wp1[i], s);
            float2 f = upk2(s);
            v[i] = f.x + f.y;
        }

        // reduce-scatter over lane bits 0..2: lane L -> qubit index L&7
#pragma unroll
        for (int w = 4; w >= 1; w >>= 1) {
            const bool hi = (lane & w) != 0;
#pragma unroll
            for (int k = 0; k < w; k++) {
                float sendv = hi ? v[k] : v[k + w];
                float keepv = hi ? v[k + w] : v[k];
                v[k] = keepv + __shfl_xor_sync(FULL, sendv, w, 32);
            }
        }
        // fold the 4 octets
        float s8 = v[0];
        s8 += __shfl_xor_sync(FULL, s8, 8, 32);
        s8 += __shfl_xor_sync(FULL, s8, 16, 32);

        if (lane < 8) part[rloc][lane][wid] = s8;
    }
    __syncthreads();

    // Quantum: one thread per (row, qubit)
    if (threadIdx.x < 128) {
        const int row = threadIdx.x >> 3;
        const int qi  = threadIdx.x & 7;

        const float4 pa = *(const float4*)&part[row][qi][0];
        const float4 pb = *(const float4*)&part[row][qi][4];
        const float a = ((pa.x + pa.y) + (pa.z + pa.w))
                      + ((pb.x + pb.y) + (pb.z + pb.w)) + __ldg(b1 + qi);

        const float phi   = __ldg(qp + 3 * qi);
        const float theta = __ldg(qp + 3 * qi + 1);
        const float k1 = cosf(theta);
        const float k2 = sinf(theta) * sinf(phi);

        float sa, ca;
        __sincosf(a, &sa, &ca);
        const float z = k1 * ca - k2 * sa;

        // inclusive prefix product over each 8-lane octet
        float p = z;
#pragma unroll
        for (int d = 1; d < 8; d <<= 1) {
            float t = __shfl_up_sync(FULL, p, d, 8);
            if (qi >= d) p *= t;
        }
        // second scan with z0 -> 1 for qout[0] = z1..z7
        float wv = (qi == 0) ? 1.0f : z;
#pragma unroll
        for (int d = 1; d < 8; d <<= 1) {
            float t = __shfl_up_sync(FULL, wv, d, 8);
            if (qi >= d) wv *= t;
        }
        const float pb7 = __shfl_sync(FULL, wv, 7, 8);
        const float qv  = (qi == 0) ? pb7 : p;

        // coalesced 512B store of this block's qout tile
        g_qout[(size_t)rowblk * 8 + threadIdx.x] = qv;
    }
}

// ================= Kernel 2: GEMM2 streaming =================
// 16 rows per 256-thread block, grid = nrows/16. Thread t owns output columns
// e0 = t*4 (float4). W2[e0..e0+3][0..7] register-resident (32 regs), loaded once.
// Per row: 2 broadcast LDS.128 of qout, 16 FFMA2 + 4 adds, 1 coalesced STG.128.
__global__ void __launch_bounds__(256, 4)
ffq_k2(const float* __restrict__ W2, const float* __restrict__ b2,
       float* __restrict__ out, int nrows)
{
    __shared__ __align__(16) float sq[16][8];

    const int tid = threadIdx.x;
    const int rowblk = blockIdx.x * 16;
    const int e0 = tid * 4;

    // stage this block's qout tile (128 floats, coalesced)
    if (tid < 128) sq[tid >> 3][tid & 7] = g_qout[(size_t)rowblk * 8 + tid];

    // W2 slice: 4 rows of 8 -> 16 u64, reg-resident
    u64 w2r[4][4];
#pragma unroll
    for (int k = 0; k < 4; k++) {
        longlong2 a = __ldg((const longlong2*)(W2 + (size_t)(e0 + k) * 8));
        longlong2 b = __ldg((const longlong2*)(W2 + (size_t)(e0 + k) * 8 + 4));
        w2r[k][0] = (u64)a.x;
        w2r[k][1] = (u64)a.y;
        w2r[k][2] = (u64)b.x;
        w2r[k][3] = (u64)b.y;
    }
    const float4 bv = __ldg((const float4*)(b2 + e0));
    __syncthreads();

#pragma unroll 4
    for (int rloc = 0; rloc < 16; rloc++) {
        const int row = rowblk + rloc;
        if (row >= nrows) break;

        const longlong2* sp = (const longlong2*)sq[rloc];   // broadcast LDS.128 x2
        longlong2 qa = sp[0], qb = sp[1];
        const u64 qd0 = (u64)qa.x, qd1 = (u64)qa.y;
        const u64 qd2 = (u64)qb.x, qd3 = (u64)qb.y;

        float o[4];
#pragma unroll
        for (int k = 0; k < 4; k++) {
            u64 s = mul2(w2r[k][0], qd0);
            s = fma2(w2r[k][1], qd1, s);
            s = fma2(w2r[k][2], qd2, s);
            s = fma2(w2r[k][3], qd3, s);
            float2 f = upk2(s);
            o[k] = f.x + f.y;
        }
        float4 ov = make_float4(o[0] + bv.x, o[1] + bv.y, o[2] + bv.z, o[3] + bv.w);
        *((float4*)(out + (size_t)row * 1024 + e0)) = ov;
    }
}

extern "C" void kernel_launch(void* const* d_in, const int* in_sizes, int n_in,
                              void* d_out, int out_size)
{
    const float* x  = (const float*)d_in[0];
    const float* W1 = (const float*)d_in[1];
    const float* b1 = (const float*)d_in[2];
    const float* qp = (const float*)d_in[3];
    const float* W2 = (const float*)d_in[4];
    const float* b2 = (const float*)d_in[5];
    float* out = (float*)d_out;

    const int nrows = in_sizes[0] / 1024;            // batch * seq_len
    const int nblocks = (nrows + 15) / 16;

    ffq_k1<<<nblocks, 256>>>(x, W1, b1, qp, nrows);
    ffq_k2<<<nblocks, 256>>>(W2, b2, out, nrows);
}

// round 6
// speedup vs baseline: 1.4830x; 1.4830x over previous
#include <cuda_runtime.h>

#define FULL 0xffffffffu
typedef unsigned long long u64;

// ---- packed f32x2 helpers (Blackwell FFMA2 — only reachable via PTX) ----
__device__ __forceinline__ float2 upk2(u64 p) {
    float2 v;
    asm("mov.b64 {%0, %1}, %2;" : "=f"(v.x), "=f"(v.y) : "l"(p));
    return v;
}
__device__ __forceinline__ u64 fma2(u64 a, u64 b, u64 c) {
    u64 d;
    asm("fma.rn.f32x2 %0, %1, %2, %3;" : "=l"(d) : "l"(a), "l"(b), "l"(c));
    return d;
}
__device__ __forceinline__ u64 mul2(u64 a, u64 b) {
    u64 d;
    asm("mul.rn.f32x2 %0, %1, %2;" : "=l"(d) : "l"(a), "l"(b));
    return d;
}

// Fused split-K kernel, 8 rows per 256-thread block, grid = nrows/8 (1024).
// Phase 1: warp w owns j-slice [w*128, w*128+128); W1 slice register-resident.
//   Per row per lane: 1 LDG.128 (x), 16 FFMA2, 9-shuffle reduce-scatter, smem partial.
// Quantum (threads 0..63, one per (row,qubit)): closed-form
//   z = cos(th)cos(a) - sin(th)sin(phi)sin(a); CNOT ring conjugated to Z-strings
//   -> qout[0]=z1..z7, qout[i]=z0..zi via octet prefix products.
// Phase 2: e = wid*128 + c*32 + lane (c=0..3); W2 register-resident; per row:
//   2 broadcast LDS.128 + 20 f32x2 ops + 4 coalesced STG.32.
__global__ void __launch_bounds__(256, 3)
ffq_kernel(const float* __restrict__ x,  const float* __restrict__ W1,
           const float* __restrict__ b1, const float* __restrict__ qp,
           const float* __restrict__ W2, const float* __restrict__ b2,
           float* __restrict__ out, int nrows)
{
    __shared__ __align__(16) float part[8][8][8];   // [row][qubit][warp]
    __shared__ __align__(16) float sq[8][8];        // qout per row

    const int lane = threadIdx.x & 31;
    const int wid  = threadIdx.x >> 5;
    const int rowblk = blockIdx.x * 8;

    const int j0 = wid * 128 + lane * 4;   // this lane's 4 j's

    // ---------------- Phase 1: split-K GEMM1, W1 reg-resident ----------------
    u64 wp0[8], wp1[8];
#pragma unroll
    for (int i = 0; i < 8; i++) {
        longlong2 w = __ldg((const longlong2*)(W1 + (size_t)i * 1024 + j0));
        wp0[i] = (u64)w.x;
        wp1[i] = (u64)w.y;
    }

#pragma unroll 4
    for (int rloc = 0; rloc < 8; rloc++) {
        const int row = min(rowblk + rloc, nrows - 1);
        longlong2 xv = __ldg((const longlong2*)(x + (size_t)row * 1024 + j0));
        const u64 x0 = (u64)xv.x, x1 = (u64)xv.y;

        float v[8];
#pragma unroll
        for (int i = 0; i < 8; i++) {
            u64 s = mul2(x0, wp0[i]);
            s = fma2(x1, wp1[i], s);
            float2 f = upk2(s);
            v[i] = f.x + f.y;
        }

        // reduce-scatter over lane bits 0..2: lane L -> qubit index L&7
#pragma unroll
        for (int w = 4; w >= 1; w >>= 1) {
            const bool hi = (lane & w) != 0;
#pragma unroll
            for (int k = 0; k < w; k++) {
                float sendv = hi ? v[k] : v[k + w];
                float keepv = hi ? v[k + w] : v[k];
                v[k] = keepv + __shfl_xor_sync(FULL, sendv, w, 32);
            }
        }
        // fold the 4 octets
        float s8 = v[0];
        s8 += __shfl_xor_sync(FULL, s8, 8, 32);
        s8 += __shfl_xor_sync(FULL, s8, 16, 32);

        if (lane < 8) part[rloc][lane][wid] = s8;
    }
    __syncthreads();

    // ---------------- Quantum: one thread per (row, qubit) ----------------
    if (threadIdx.x < 64) {
        const int row = threadIdx.x >> 3;
        const int qi  = threadIdx.x & 7;

        const float4 pa = *(const float4*)&part[row][qi][0];
        const float4 pb = *(const float4*)&part[row][qi][4];
        const float a = ((pa.x + pa.y) + (pa.z + pa.w))
                      + ((pb.x + pb.y) + (pb.z + pb.w)) + __ldg(b1 + qi);

        const float phi   = __ldg(qp + 3 * qi);
        const float theta = __ldg(qp + 3 * qi + 1);
        const float k1 = cosf(theta);
        const float k2 = sinf(theta) * sinf(phi);

        float sa, ca;
        __sincosf(a, &sa, &ca);
        const float z = k1 * ca - k2 * sa;

        // inclusive prefix product over each 8-lane octet
        float p = z;
#pragma unroll
        for (int d = 1; d < 8; d <<= 1) {
            float t = __shfl_up_sync(FULL, p, d, 8);
            if (qi >= d) p *= t;
        }
        // second scan with z0 -> 1 for qout[0] = z1..z7
        float wv = (qi == 0) ? 1.0f : z;
#pragma unroll
        for (int d = 1; d < 8; d <<= 1) {
            float t = __shfl_up_sync(FULL, wv, d, 8);
            if (qi >= d) wv *= t;
        }
        const float pb7 = __shfl_sync(FULL, wv, 7, 8);
        sq[row][qi] = (qi == 0) ? pb7 : p;
    }
    __syncthreads();

    // ---------------- Phase 2: GEMM2, W2 reg-resident, contiguous loads ----------------
    u64 w2r[4][4];
    float bv[4];
#pragma unroll
    for (int c = 0; c < 4; c++) {
        const int e = wid * 128 + c * 32 + lane;
        longlong2 a = __ldg((const longlong2*)(W2 + (size_t)e * 8));
        longlong2 b = __ldg((const longlong2*)(W2 + (size_t)e * 8 + 4));
        w2r[c][0] = (u64)a.x;
        w2r[c][1] = (u64)a.y;
        w2r[c][2] = (u64)b.x;
        w2r[c][3] = (u64)b.y;
        bv[c] = __ldg(b2 + e);
    }

#pragma unroll 4
    for (int rloc = 0; rloc < 8; rloc++) {
        const int row = rowblk + rloc;
        if (row >= nrows) break;

        const longlong2* sp = (const longlong2*)sq[rloc];   // broadcast LDS.128 x2
        longlong2 qa = sp[0], qb = sp[1];
        const u64 qd0 = (u64)qa.x, qd1 = (u64)qa.y;
        const u64 qd2 = (u64)qb.x, qd3 = (u64)qb.y;

        float* orow = out + (size_t)row * 1024 + wid * 128 + lane;
#pragma unroll
        for (int c = 0; c < 4; c++) {
            u64 s = mul2(w2r[c][0], qd0);
            s = fma2(w2r[c][1], qd1, s);
            s = fma2(w2r[c][2], qd2, s);
            s = fma2(w2r[c][3], qd3, s);
            float2 f = upk2(s);
            orow[c * 32] = (f.x + f.y) + bv[c];
        }
    }
}

extern "C" void kernel_launch(void* const* d_in, const int* in_sizes, int n_in,
                              void* d_out, int out_size)
{
    const float* x  = (const float*)d_in[0];
    const float* W1 = (const float*)d_in[1];
    const float* b1 = (const float*)d_in[2];
    const float* qp = (const float*)d_in[3];
    const float* W2 = (const float*)d_in[4];
    const float* b2 = (const float*)d_in[5];
    float* out = (float*)d_out;

    const int nrows = in_sizes[0] / 1024;            // batch * seq_len
    const int nblocks = (nrows + 7) / 8;             // 8 rows per block

    ffq_kernel<<<nblocks, 256>>>(x, W1, b1, qp, W2, b2, out, nrows);
}